// round 6
// baseline (speedup 1.0000x reference)
#include <cuda_runtime.h>
#include <cstdint>

#define DIN    128
#define DOUT   128
#define TILE   64
#define THREADS 256

// ---- smem byte offsets (per CTA ~100KB -> 2 CTAs/SM) ----
#define OFF_WH   0              // 8s x 8p x 32 lanes x 16B = 32KB
#define OFF_WL   32768
#define OFF_AH   65536          // 4f x 8s x 32 x 16B = 16KB
#define OFF_AL   81920
#define OFF_BIAS 98304          // 128 f32
#define OFF_B2   98816
#define OFF_XN2P 98832          // [64][2] f32
#define OFF_RS2  99344          // [64][4] f32
#define OFF_RSB  100368         // [64][4] f32
#define OFF_CA   101392         // [64] f32
#define OFF_CB   101648         // [64] f32
#define SMEM_TOTAL 101904

__device__ __forceinline__ uint32_t packbf(float hi, float lo) {
    uint32_t r; asm("cvt.rn.bf16x2.f32 %0, %1, %2;" : "=r"(r) : "f"(hi), "f"(lo)); return r;
}
__device__ __forceinline__ float lo_bf(uint32_t p) { return __uint_as_float(p << 16); }
__device__ __forceinline__ float hi_bf(uint32_t p) { return __uint_as_float(p & 0xffff0000u); }

__device__ __forceinline__ void mma_bf16(float4& d, const uint4& a, uint32_t b0, uint32_t b1) {
    asm volatile("mma.sync.aligned.m16n8k16.row.col.f32.bf16.bf16.f32 "
        "{%0,%1,%2,%3}, {%4,%5,%6,%7}, {%8,%9}, {%0,%1,%2,%3};"
        : "+f"(d.x), "+f"(d.y), "+f"(d.z), "+f"(d.w)
        : "r"(a.x), "r"(a.y), "r"(a.z), "r"(a.w), "r"(b0), "r"(b1));
}
__device__ __forceinline__ void pf_l2(const void* p) {
    asm volatile("prefetch.global.L2 [%0];" :: "l"(p));
}

extern "C" __global__ void __launch_bounds__(THREADS, 2)
mobius_mma3_kernel(const float* __restrict__ X,
                   const float* __restrict__ W,
                   const float* __restrict__ bias,
                   float* __restrict__ out,
                   int nrows)
{
    extern __shared__ __align__(16) char smem[];
    float* sbias = (float*)(smem + OFF_BIAS);
    float* sB2   = (float*)(smem + OFF_B2);
    float* xn2p  = (float*)(smem + OFF_XN2P);
    float* rs2   = (float*)(smem + OFF_RS2);
    float* rsb   = (float*)(smem + OFF_RSB);
    float* cA    = (float*)(smem + OFF_CA);
    float* cB    = (float*)(smem + OFF_CB);

    const int tid  = threadIdx.x;
    const int lane = tid & 31;
    const int wid  = tid >> 5;        // 8 warps
    const int g    = lane >> 2;
    const int cg   = lane & 3;
    const int wm   = wid >> 2;        // 0..1 (m-half: 32 rows)
    const int wn   = wid & 3;         // 0..3 (n-quarter: 32 cols)
    const int f    = wid >> 1;        // conversion frag-row 0..3
    const int sh   = (wid & 1) * 4;   // conversion s-half

    if (tid < 128) sbias[tid] = bias[tid];

    // ---- W conversion (once): warp wid = k-step s ----
    {
        const float* wp0 = W + wid * 16 + 2 * cg;
        #pragma unroll
        for (int nt = 0; nt < 16; nt++) {
            int n = nt * 8 + g;
            const float* wp = wp0 + n * DIN;
            float2 u0 = *(const float2*)(wp);
            float2 u1 = *(const float2*)(wp + 8);
            uint32_t h0 = packbf(u0.y, u0.x);
            uint32_t h1 = packbf(u1.y, u1.x);
            uint32_t l0 = packbf(u0.y - hi_bf(h0), u0.x - lo_bf(h0));
            uint32_t l1 = packbf(u1.y - hi_bf(h1), u1.x - lo_bf(h1));
            int p = nt >> 1, half = nt & 1;
            int off = ((wid * 8 + p) * 32 + lane) * 16 + half * 8;
            uint2 vh; vh.x = h0; vh.y = h1;
            uint2 vl; vl.x = l0; vl.y = l1;
            *(uint2*)(smem + OFF_WH + off) = vh;
            *(uint2*)(smem + OFF_WL + off) = vl;
        }
    }
    __syncthreads();
    if (tid < 32) {
        float s = 0.f;
        #pragma unroll
        for (int i = 0; i < 4; i++) { float v = sbias[tid + 32 * i]; s = fmaf(v, v, s); }
        #pragma unroll
        for (int o = 16; o; o >>= 1) s += __shfl_xor_sync(0xffffffffu, s, o);
        if (tid == 0) *sB2 = s;
    }
    __syncthreads();

    // bias fragment for this warp's n32
    float2 bj[4];
    #pragma unroll
    for (int j = 0; j < 4; j++)
        bj[j] = *(const float2*)(sbias + wn * 32 + j * 8 + 2 * cg);

    const int ntiles = nrows / TILE;

    for (int t = blockIdx.x; t < ntiles; t += gridDim.x) {
        const long long rowbase = (long long)t * TILE;

        // ---- A conversion: warp -> frag-row f, k-steps [sh, sh+4) ----
        {
            const float* p0 = X + (rowbase + f * 16 + g) * DIN + 2 * cg + 16 * sh;
            const float* p1 = p0 + 8 * DIN;
            float xa0 = 0.f, xa1 = 0.f;
            #pragma unroll
            for (int s2 = 0; s2 < 4; s2++) {
                float2 v00 = *(const float2*)(p0 + 16 * s2);
                float2 v01 = *(const float2*)(p0 + 16 * s2 + 8);
                float2 v10 = *(const float2*)(p1 + 16 * s2);
                float2 v11 = *(const float2*)(p1 + 16 * s2 + 8);
                xa0 = fmaf(v00.x, v00.x, xa0); xa0 = fmaf(v00.y, v00.y, xa0);
                xa0 = fmaf(v01.x, v01.x, xa0); xa0 = fmaf(v01.y, v01.y, xa0);
                xa1 = fmaf(v10.x, v10.x, xa1); xa1 = fmaf(v10.y, v10.y, xa1);
                xa1 = fmaf(v11.x, v11.x, xa1); xa1 = fmaf(v11.y, v11.y, xa1);
                uint4 h, l;
                h.x = packbf(v00.y, v00.x);
                h.y = packbf(v10.y, v10.x);
                h.z = packbf(v01.y, v01.x);
                h.w = packbf(v11.y, v11.x);
                l.x = packbf(v00.y - hi_bf(h.x), v00.x - lo_bf(h.x));
                l.y = packbf(v10.y - hi_bf(h.y), v10.x - lo_bf(h.y));
                l.z = packbf(v01.y - hi_bf(h.z), v01.x - lo_bf(h.z));
                l.w = packbf(v11.y - hi_bf(h.w), v11.x - lo_bf(h.w));
                int off = ((f * 8 + sh + s2) * 32 + lane) * 16;
                *(uint4*)(smem + OFF_AH + off) = h;
                *(uint4*)(smem + OFF_AL + off) = l;
            }
            xa0 += __shfl_xor_sync(0xffffffffu, xa0, 1);
            xa0 += __shfl_xor_sync(0xffffffffu, xa0, 2);
            xa1 += __shfl_xor_sync(0xffffffffu, xa1, 1);
            xa1 += __shfl_xor_sync(0xffffffffu, xa1, 2);
            if (cg == 0) {
                xn2p[(f * 16 + g) * 2 + (wid & 1)]     = xa0;
                xn2p[(f * 16 + g + 8) * 2 + (wid & 1)] = xa1;
            }
        }

        // ---- L2 prefetch next tile (32KB) ----
        {
            int tn = t + gridDim.x;
            if (tn < ntiles)
                pf_l2((const char*)(X + (long long)tn * TILE * DIN) + tid * 128);
        }
        __syncthreads();   // frags + xn2 visible

        // ---- mainloop: warp tile m32 x n32, 3-pass bf16 ----
        float4 acc[2][4];
        #pragma unroll
        for (int i = 0; i < 2; i++)
            #pragma unroll
            for (int j = 0; j < 4; j++) acc[i][j] = make_float4(0.f, 0.f, 0.f, 0.f);

        #pragma unroll
        for (int s = 0; s < 8; s++) {
            uint4 ah[2], wh[2], al[2], wl[2];
            #pragma unroll
            for (int i = 0; i < 2; i++)
                ah[i] = *(const uint4*)(smem + OFF_AH + (((wm * 2 + i) * 8 + s) * 32 + lane) * 16);
            #pragma unroll
            for (int u = 0; u < 2; u++)
                wh[u] = *(const uint4*)(smem + OFF_WH + (((s * 8 + wn * 2 + u) * 32 + lane) * 16));
            #pragma unroll
            for (int i = 0; i < 2; i++)
                #pragma unroll
                for (int u = 0; u < 2; u++) {
                    mma_bf16(acc[i][2*u],   ah[i], wh[u].x, wh[u].y);
                    mma_bf16(acc[i][2*u+1], ah[i], wh[u].z, wh[u].w);
                }
            #pragma unroll
            for (int i = 0; i < 2; i++)
                al[i] = *(const uint4*)(smem + OFF_AL + (((wm * 2 + i) * 8 + s) * 32 + lane) * 16);
            #pragma unroll
            for (int i = 0; i < 2; i++)
                #pragma unroll
                for (int u = 0; u < 2; u++) {
                    mma_bf16(acc[i][2*u],   al[i], wh[u].x, wh[u].y);
                    mma_bf16(acc[i][2*u+1], al[i], wh[u].z, wh[u].w);
                }
            #pragma unroll
            for (int u = 0; u < 2; u++)
                wl[u] = *(const uint4*)(smem + OFF_WL + (((s * 8 + wn * 2 + u) * 32 + lane) * 16));
            #pragma unroll
            for (int i = 0; i < 2; i++)
                #pragma unroll
                for (int u = 0; u < 2; u++) {
                    mma_bf16(acc[i][2*u],   ah[i], wl[u].x, wl[u].y);
                    mma_bf16(acc[i][2*u+1], ah[i], wl[u].z, wl[u].w);
                }
        }

        // ---- epilogue reductions: ||Mx||^2 and <Mx,bias> per row ----
        #pragma unroll
        for (int i = 0; i < 2; i++) {
            float s2r0 = 0.f, s2r1 = 0.f, sbr0 = 0.f, sbr1 = 0.f;
            #pragma unroll
            for (int j = 0; j < 4; j++) {
                float4 d = acc[i][j];
                s2r0 = fmaf(d.x, d.x, s2r0); s2r0 = fmaf(d.y, d.y, s2r0);
                s2r1 = fmaf(d.z, d.z, s2r1); s2r1 = fmaf(d.w, d.w, s2r1);
                sbr0 = fmaf(d.x, bj[j].x, sbr0); sbr0 = fmaf(d.y, bj[j].y, sbr0);
                sbr1 = fmaf(d.z, bj[j].x, sbr1); sbr1 = fmaf(d.w, bj[j].y, sbr1);
            }
            s2r0 += __shfl_xor_sync(0xffffffffu, s2r0, 1);
            s2r0 += __shfl_xor_sync(0xffffffffu, s2r0, 2);
            s2r1 += __shfl_xor_sync(0xffffffffu, s2r1, 1);
            s2r1 += __shfl_xor_sync(0xffffffffu, s2r1, 2);
            sbr0 += __shfl_xor_sync(0xffffffffu, sbr0, 1);
            sbr0 += __shfl_xor_sync(0xffffffffu, sbr0, 2);
            sbr1 += __shfl_xor_sync(0xffffffffu, sbr1, 1);
            sbr1 += __shfl_xor_sync(0xffffffffu, sbr1, 2);
            if (cg == 0) {
                int r0 = wm * 32 + i * 16 + g;
                rs2[r0 * 4 + wn]       = s2r0;
                rs2[(r0 + 8) * 4 + wn] = s2r1;
                rsb[r0 * 4 + wn]       = sbr0;
                rsb[(r0 + 8) * 4 + wn] = sbr1;
            }
        }
        __syncthreads();

        // ---- per-row scalar math -> coefficients ----
        if (tid < TILE) {
            int r = tid;
            float4 a4 = *(const float4*)(rs2 + r * 4);
            float4 b4 = *(const float4*)(rsb + r * 4);
            float mxn2 = (a4.x + a4.y) + (a4.z + a4.w);
            float dotb = (b4.x + b4.y) + (b4.z + b4.w);
            float xnq  = xn2p[r * 2] + xn2p[r * 2 + 1];
            float b2c = *sB2;
            float xn  = fmaxf(sqrtf(xnq),  1e-15f);
            float mxn = fmaxf(sqrtf(mxn2), 1e-15f);
            float u   = fminf(xn, 1.0f - 1e-7f);
            float at  = 0.5f * (log1pf(u) - log1pf(-u));
            float sc  = tanhf(mxn / xn * at) / mxn;
            if (mxn <= 1e-10f) sc = 0.0f;
            float xy    = sc * dotb;
            float y2    = sc * sc * mxn2;
            float alpha = 1.0f + 2.0f * xy + b2c;
            float beta  = 1.0f - y2;
            float den   = fmaxf(1.0f + 2.0f * xy + y2 * b2c, 1e-15f);
            float A  = sc * alpha / den;
            float Bc = beta / den;
            float o2 = A * A * mxn2 + 2.0f * A * Bc * dotb + Bc * Bc * b2c;
            float on = fmaxf(sqrtf(o2), 1e-15f);
            float mxv = 1.0f - 1e-5f;
            float fpr = (on > mxv) ? (mxv / on) : 1.0f;
            cA[r] = A * fpr;
            cB[r] = Bc * fpr;
        }
        __syncthreads();

        // ---- stores: out = A[r]*Mx + B[r]*bias straight from regs ----
        {
            #pragma unroll
            for (int i = 0; i < 2; i++) {
                int r0 = wm * 32 + i * 16 + g;     // tile-local row
                float A0 = cA[r0],     B0 = cB[r0];
                float A1 = cA[r0 + 8], B1 = cB[r0 + 8];
                float* op0 = out + (rowbase + r0) * DOUT + wn * 32 + 2 * cg;
                float* op1 = op0 + 8 * DOUT;
                #pragma unroll
                for (int j = 0; j < 4; j++) {
                    float4 d = acc[i][j];
                    float2 o0, o1;
                    o0.x = fmaf(A0, d.x, B0 * bj[j].x);
                    o0.y = fmaf(A0, d.y, B0 * bj[j].y);
                    o1.x = fmaf(A1, d.z, B1 * bj[j].x);
                    o1.y = fmaf(A1, d.w, B1 * bj[j].y);
                    *(float2*)(op0 + j * 8) = o0;
                    *(float2*)(op1 + j * 8) = o1;
                }
            }
        }
        // next iter: conversion rewrites AH/AL only after all warps passed
        // the two barriers above (mainloop reads are complete).
    }
}

extern "C" void kernel_launch(void* const* d_in, const int* in_sizes, int n_in,
                              void* d_out, int out_size) {
    const float* X    = (const float*)d_in[0];
    const float* W    = (const float*)d_in[1];
    const float* bias = (const float*)d_in[2];
    float* out = (float*)d_out;

    int nrows = in_sizes[0] / DIN;

    cudaFuncSetAttribute(mobius_mma3_kernel,
                         cudaFuncAttributeMaxDynamicSharedMemorySize, SMEM_TOTAL);

    int nsm = 148;
    cudaDeviceGetAttribute(&nsm, cudaDevAttrMultiProcessorCount, 0);
    int ntiles = nrows / TILE;
    int grid = 2 * nsm;
    if (grid > ntiles) grid = ntiles;

    mobius_mma3_kernel<<<grid, THREADS, SMEM_TOTAL>>>(X, W, bias, out, nrows);
}

// round 7
// speedup vs baseline: 1.1030x; 1.1030x over previous
#include <cuda_runtime.h>
#include <cuda_fp16.h>
#include <cstdint>

#define DIN    128
#define DOUT   128
#define TILE   64
#define THREADS 256
#define SPAD   132

// ---- smem byte offsets (per CTA ~103KB -> 2 CTAs/SM) ----
#define OFF_WH    0               // 8s x 8p x 32 lanes x 16B = 32KB (fp16 W)
#define OFF_AH    32768           // 4f x 8s x 32 x 16B = 16KB
#define OFF_AL    49152
#define OFF_STAGE 65536           // 64 x 132 f32 = 33792
#define OFF_BIAS  99328
#define OFF_B2    99840
#define OFF_XN2P  99856           // [64][2]
#define OFF_RS2   100368          // [64][4]
#define OFF_RSB   101392
#define OFF_CA    102416
#define OFF_CB    102672
#define SMEM_TOTAL 102928

__device__ __forceinline__ unsigned smem_u32(const void* p) {
    return (unsigned)__cvta_generic_to_shared(p);
}
__device__ __forceinline__ void cp_async16(unsigned dst, const void* src) {
    asm volatile("cp.async.ca.shared.global [%0], [%1], 16;\n" :: "r"(dst), "l"(src));
}
__device__ __forceinline__ void cp_commit() { asm volatile("cp.async.commit_group;\n"); }
__device__ __forceinline__ void cp_wait0()  { asm volatile("cp.async.wait_group 0;\n"); }

// pack two f32 -> f16x2 (hi arg -> upper 16 bits)
__device__ __forceinline__ uint32_t packh(float hi, float lo) {
    uint32_t r; asm("cvt.rn.f16x2.f32 %0, %1, %2;" : "=r"(r) : "f"(hi), "f"(lo)); return r;
}
__device__ __forceinline__ float2 unph(uint32_t p) {
    __half2 h = *(__half2*)&p;
    return make_float2(__half2float(h.x), __half2float(h.y));  // .x = lower 16
}

__device__ __forceinline__ void mma_f16(float4& d, const uint4& a, uint32_t b0, uint32_t b1) {
    asm volatile("mma.sync.aligned.m16n8k16.row.col.f32.f16.f16.f32 "
        "{%0,%1,%2,%3}, {%4,%5,%6,%7}, {%8,%9}, {%0,%1,%2,%3};"
        : "+f"(d.x), "+f"(d.y), "+f"(d.z), "+f"(d.w)
        : "r"(a.x), "r"(a.y), "r"(a.z), "r"(a.w), "r"(b0), "r"(b1));
}

extern "C" __global__ void __launch_bounds__(THREADS, 2)
mobius_mma4_kernel(const float* __restrict__ X,
                   const float* __restrict__ W,
                   const float* __restrict__ bias,
                   float* __restrict__ out,
                   int nrows)
{
    extern __shared__ __align__(16) char smem[];
    const unsigned sbase = smem_u32(smem);
    float* stage = (float*)(smem + OFF_STAGE);
    float* sbias = (float*)(smem + OFF_BIAS);
    float* sB2   = (float*)(smem + OFF_B2);
    float* xn2p  = (float*)(smem + OFF_XN2P);
    float* rs2   = (float*)(smem + OFF_RS2);
    float* rsb   = (float*)(smem + OFF_RSB);
    float* cA    = (float*)(smem + OFF_CA);
    float* cB    = (float*)(smem + OFF_CB);

    const int tid  = threadIdx.x;
    const int lane = tid & 31;
    const int wid  = tid >> 5;
    const int g    = lane >> 2;
    const int cg   = lane & 3;
    const int wm   = wid >> 2;        // m-half (32 rows)
    const int wn   = wid & 3;         // n-quarter (32 cols)
    const int f    = wid >> 1;        // conversion frag-row 0..3
    const int sh   = (wid & 1) * 4;   // conversion s-half

    const int ntiles = nrows / TILE;

    // ---- prefetch first X tile into stage ----
    if (blockIdx.x < ntiles) {
        const float* src = X + (long long)blockIdx.x * TILE * DIN;
        #pragma unroll
        for (int i = 0; i < 8; i++) {
            int q = tid + THREADS * i;      // 2048 float4s
            int b = q >> 5, k4 = q & 31;
            cp_async16(sbase + OFF_STAGE + (b * SPAD + k4 * 4) * 4,
                       src + b * DIN + k4 * 4);
        }
    }
    cp_commit();

    if (tid < 128) sbias[tid] = bias[tid];

    // ---- W conversion (once): warp wid = k-step s; fp16 hi only ----
    {
        const float* wp0 = W + wid * 16 + 2 * cg;
        #pragma unroll
        for (int nt = 0; nt < 16; nt++) {
            int n = nt * 8 + g;
            const float* wp = wp0 + n * DIN;
            float2 u0 = *(const float2*)(wp);
            float2 u1 = *(const float2*)(wp + 8);
            uint2 vh;
            vh.x = packh(u0.y, u0.x);
            vh.y = packh(u1.y, u1.x);
            int p = nt >> 1, half = nt & 1;
            *(uint2*)(smem + OFF_WH + ((wid * 8 + p) * 32 + lane) * 16 + half * 8) = vh;
        }
    }
    __syncthreads();
    if (tid < 32) {
        float s = 0.f;
        #pragma unroll
        for (int i = 0; i < 4; i++) { float v = sbias[tid + 32 * i]; s = fmaf(v, v, s); }
        #pragma unroll
        for (int o = 16; o; o >>= 1) s += __shfl_xor_sync(0xffffffffu, s, o);
        if (tid == 0) *sB2 = s;
    }
    __syncthreads();

    float2 bj[4];
    #pragma unroll
    for (int j = 0; j < 4; j++)
        bj[j] = *(const float2*)(sbias + wn * 32 + j * 8 + 2 * cg);

    for (int t = blockIdx.x; t < ntiles; t += gridDim.x) {
        const long long rowbase = (long long)t * TILE;

        cp_wait0();
        __syncthreads();   // stage(t) complete & visible to all

        // ---- A conversion (smem stage -> fp16 hi/lo frags) + xn2 ----
        {
            const float* p0 = stage + (f * 16 + g) * SPAD + 2 * cg + 16 * sh;
            const float* p1 = p0 + 8 * SPAD;
            float xa0 = 0.f, xa1 = 0.f;
            #pragma unroll
            for (int s2 = 0; s2 < 4; s2++) {
                float2 v00 = *(const float2*)(p0 + 16 * s2);
                float2 v01 = *(const float2*)(p0 + 16 * s2 + 8);
                float2 v10 = *(const float2*)(p1 + 16 * s2);
                float2 v11 = *(const float2*)(p1 + 16 * s2 + 8);
                xa0 = fmaf(v00.x, v00.x, xa0); xa0 = fmaf(v00.y, v00.y, xa0);
                xa0 = fmaf(v01.x, v01.x, xa0); xa0 = fmaf(v01.y, v01.y, xa0);
                xa1 = fmaf(v10.x, v10.x, xa1); xa1 = fmaf(v10.y, v10.y, xa1);
                xa1 = fmaf(v11.x, v11.x, xa1); xa1 = fmaf(v11.y, v11.y, xa1);
                uint4 h, l;
                h.x = packh(v00.y, v00.x);
                h.y = packh(v10.y, v10.x);
                h.z = packh(v01.y, v01.x);
                h.w = packh(v11.y, v11.x);
                float2 e;
                e = unph(h.x); l.x = packh(v00.y - e.y, v00.x - e.x);
                e = unph(h.y); l.y = packh(v10.y - e.y, v10.x - e.x);
                e = unph(h.z); l.z = packh(v01.y - e.y, v01.x - e.x);
                e = unph(h.w); l.w = packh(v11.y - e.y, v11.x - e.x);
                int off = ((f * 8 + sh + s2) * 32 + lane) * 16;
                *(uint4*)(smem + OFF_AH + off) = h;
                *(uint4*)(smem + OFF_AL + off) = l;
            }
            xa0 += __shfl_xor_sync(0xffffffffu, xa0, 1);
            xa0 += __shfl_xor_sync(0xffffffffu, xa0, 2);
            xa1 += __shfl_xor_sync(0xffffffffu, xa1, 1);
            xa1 += __shfl_xor_sync(0xffffffffu, xa1, 2);
            if (cg == 0) {
                xn2p[(f * 16 + g) * 2 + (wid & 1)]     = xa0;
                xn2p[(f * 16 + g + 8) * 2 + (wid & 1)] = xa1;
            }
        }
        __syncthreads();   // frags + xn2 visible; stage reads done

        // ---- issue cp.async for next tile (overlaps MMA + epilogue) ----
        {
            int tn = t + gridDim.x;
            if (tn < ntiles) {
                const float* src = X + (long long)tn * TILE * DIN;
                #pragma unroll
                for (int i = 0; i < 8; i++) {
                    int q = tid + THREADS * i;
                    int b = q >> 5, k4 = q & 31;
                    cp_async16(sbase + OFF_STAGE + (b * SPAD + k4 * 4) * 4,
                               src + b * DIN + k4 * 4);
                }
            }
            cp_commit();
        }

        // ---- mainloop: warp tile m32 x n32, 2-pass fp16 ----
        float4 acc[2][4];
        #pragma unroll
        for (int i = 0; i < 2; i++)
            #pragma unroll
            for (int j = 0; j < 4; j++) acc[i][j] = make_float4(0.f, 0.f, 0.f, 0.f);

        #pragma unroll
        for (int s = 0; s < 8; s++) {
            uint4 ah[2], wh[2], al[2];
            #pragma unroll
            for (int i = 0; i < 2; i++)
                ah[i] = *(const uint4*)(smem + OFF_AH + (((wm * 2 + i) * 8 + s) * 32 + lane) * 16);
            #pragma unroll
            for (int u = 0; u < 2; u++)
                wh[u] = *(const uint4*)(smem + OFF_WH + (((s * 8 + wn * 2 + u) * 32 + lane) * 16));
            #pragma unroll
            for (int i = 0; i < 2; i++)
                #pragma unroll
                for (int u = 0; u < 2; u++) {
                    mma_f16(acc[i][2*u],   ah[i], wh[u].x, wh[u].y);
                    mma_f16(acc[i][2*u+1], ah[i], wh[u].z, wh[u].w);
                }
            #pragma unroll
            for (int i = 0; i < 2; i++)
                al[i] = *(const uint4*)(smem + OFF_AL + (((wm * 2 + i) * 8 + s) * 32 + lane) * 16);
            #pragma unroll
            for (int i = 0; i < 2; i++)
                #pragma unroll
                for (int u = 0; u < 2; u++) {
                    mma_f16(acc[i][2*u],   al[i], wh[u].x, wh[u].y);
                    mma_f16(acc[i][2*u+1], al[i], wh[u].z, wh[u].w);
                }
        }

        // ---- epilogue reductions: ||Mx||^2 and <Mx,bias> per row ----
        #pragma unroll
        for (int i = 0; i < 2; i++) {
            float s2r0 = 0.f, s2r1 = 0.f, sbr0 = 0.f, sbr1 = 0.f;
            #pragma unroll
            for (int j = 0; j < 4; j++) {
                float4 d = acc[i][j];
                s2r0 = fmaf(d.x, d.x, s2r0); s2r0 = fmaf(d.y, d.y, s2r0);
                s2r1 = fmaf(d.z, d.z, s2r1); s2r1 = fmaf(d.w, d.w, s2r1);
                sbr0 = fmaf(d.x, bj[j].x, sbr0); sbr0 = fmaf(d.y, bj[j].y, sbr0);
                sbr1 = fmaf(d.z, bj[j].x, sbr1); sbr1 = fmaf(d.w, bj[j].y, sbr1);
            }
            s2r0 += __shfl_xor_sync(0xffffffffu, s2r0, 1);
            s2r0 += __shfl_xor_sync(0xffffffffu, s2r0, 2);
            s2r1 += __shfl_xor_sync(0xffffffffu, s2r1, 1);
            s2r1 += __shfl_xor_sync(0xffffffffu, s2r1, 2);
            sbr0 += __shfl_xor_sync(0xffffffffu, sbr0, 1);
            sbr0 += __shfl_xor_sync(0xffffffffu, sbr0, 2);
            sbr1 += __shfl_xor_sync(0xffffffffu, sbr1, 1);
            sbr1 += __shfl_xor_sync(0xffffffffu, sbr1, 2);
            if (cg == 0) {
                int r0 = wm * 32 + i * 16 + g;
                rs2[r0 * 4 + wn]       = s2r0;
                rs2[(r0 + 8) * 4 + wn] = s2r1;
                rsb[r0 * 4 + wn]       = sbr0;
                rsb[(r0 + 8) * 4 + wn] = sbr1;
            }
        }
        __syncthreads();

        // ---- per-row scalar math -> coefficients ----
        if (tid < TILE) {
            int r = tid;
            float4 a4 = *(const float4*)(rs2 + r * 4);
            float4 b4 = *(const float4*)(rsb + r * 4);
            float mxn2 = (a4.x + a4.y) + (a4.z + a4.w);
            float dotb = (b4.x + b4.y) + (b4.z + b4.w);
            float xnq  = xn2p[r * 2] + xn2p[r * 2 + 1];
            float b2c = *sB2;
            float xn  = fmaxf(sqrtf(xnq),  1e-15f);
            float mxn = fmaxf(sqrtf(mxn2), 1e-15f);
            float u   = fminf(xn, 1.0f - 1e-7f);
            float at  = 0.5f * (log1pf(u) - log1pf(-u));
            float sc  = tanhf(mxn / xn * at) / mxn;
            if (mxn <= 1e-10f) sc = 0.0f;
            float xy    = sc * dotb;
            float y2    = sc * sc * mxn2;
            float alpha = 1.0f + 2.0f * xy + b2c;
            float beta  = 1.0f - y2;
            float den   = fmaxf(1.0f + 2.0f * xy + y2 * b2c, 1e-15f);
            float A  = sc * alpha / den;
            float Bc = beta / den;
            float o2 = A * A * mxn2 + 2.0f * A * Bc * dotb + Bc * Bc * b2c;
            float on = fmaxf(sqrtf(o2), 1e-15f);
            float mxv = 1.0f - 1e-5f;
            float fpr = (on > mxv) ? (mxv / on) : 1.0f;
            cA[r] = A * fpr;
            cB[r] = Bc * fpr;
        }
        __syncthreads();

        // ---- stores: out = A[r]*Mx + B[r]*bias straight from regs ----
        {
            #pragma unroll
            for (int i = 0; i < 2; i++) {
                int r0 = wm * 32 + i * 16 + g;
                float A0 = cA[r0],     B0 = cB[r0];
                float A1 = cA[r0 + 8], B1 = cB[r0 + 8];
                float* op0 = out + (rowbase + r0) * DOUT + wn * 32 + 2 * cg;
                float* op1 = op0 + 8 * DOUT;
                #pragma unroll
                for (int j = 0; j < 4; j++) {
                    float4 d = acc[i][j];
                    float2 o0, o1;
                    o0.x = fmaf(A0, d.x, B0 * bj[j].x);
                    o0.y = fmaf(A0, d.y, B0 * bj[j].y);
                    o1.x = fmaf(A1, d.z, B1 * bj[j].x);
                    o1.y = fmaf(A1, d.w, B1 * bj[j].y);
                    *(float2*)(op0 + j * 8) = o0;
                    *(float2*)(op1 + j * 8) = o1;
                }
            }
        }
        // next iter: conversion rewrites AH/AL only after all warps have
        // passed the post-reduction barrier (mainloop reads complete).
    }
}

extern "C" void kernel_launch(void* const* d_in, const int* in_sizes, int n_in,
                              void* d_out, int out_size) {
    const float* X    = (const float*)d_in[0];
    const float* W    = (const float*)d_in[1];
    const float* bias = (const float*)d_in[2];
    float* out = (float*)d_out;

    int nrows = in_sizes[0] / DIN;

    cudaFuncSetAttribute(mobius_mma4_kernel,
                         cudaFuncAttributeMaxDynamicSharedMemorySize, SMEM_TOTAL);

    int nsm = 148;
    cudaDeviceGetAttribute(&nsm, cudaDevAttrMultiProcessorCount, 0);
    int ntiles = nrows / TILE;
    int grid = 2 * nsm;
    if (grid > ntiles) grid = ntiles;

    mobius_mma4_kernel<<<grid, THREADS, SMEM_TOTAL>>>(X, W, bias, out, nrows);
}

// round 8
// speedup vs baseline: 1.1628x; 1.0541x over previous
#include <cuda_runtime.h>
#include <cuda_fp16.h>
#include <cstdint>

#define DIN    128
#define DOUT   128
#define TILE   64
#define THREADS 256

// ---- smem layout (per CTA ~99KB -> 2 CTAs/SM) ----
#define OFF_WH     0                          // 8s x 8p x 32 x 16B = 32KB
#define AH_ST(s)   (32768 + (s)*32768)        // 16KB per stage
#define AL_ST(s)   (32768 + (s)*32768 + 16384)
#define OFF_BIAS   98304                      // 128 f32
#define OFF_B2     98816
#define OFF_XN2(s) (98832 + (s)*256)          // [64] f32 per stage
#define OFF_RS2    99344                      // [64][2] f32
#define OFF_RSB    99856
#define OFF_CA     100368
#define OFF_CB     100624
#define SMEM_TOTAL 100880

// named barriers: 1,2 = full(stage), 3,4 = empty(stage), 5 = consumer-internal
#define BAR_FULL(s)  (1 + (s))
#define BAR_EMPTY(s) (3 + (s))
#define BAR_CONS     5

__device__ __forceinline__ void bar_sync256(int id) {
    asm volatile("bar.sync %0, %1;" :: "r"(id), "r"(256) : "memory");
}
__device__ __forceinline__ void bar_arrive256(int id) {
    asm volatile("bar.arrive %0, %1;" :: "r"(id), "r"(256) : "memory");
}
__device__ __forceinline__ void bar_sync128(int id) {
    asm volatile("bar.sync %0, %1;" :: "r"(id), "r"(128) : "memory");
}

__device__ __forceinline__ uint32_t packh(float hi, float lo) {
    uint32_t r; asm("cvt.rn.f16x2.f32 %0, %1, %2;" : "=r"(r) : "f"(hi), "f"(lo)); return r;
}
__device__ __forceinline__ float2 unph(uint32_t p) {
    __half2 h = *(__half2*)&p;
    return make_float2(__half2float(h.x), __half2float(h.y));
}
__device__ __forceinline__ void mma_f16(float4& d, const uint4& a, uint32_t b0, uint32_t b1) {
    asm volatile("mma.sync.aligned.m16n8k16.row.col.f32.f16.f16.f32 "
        "{%0,%1,%2,%3}, {%4,%5,%6,%7}, {%8,%9}, {%0,%1,%2,%3};"
        : "+f"(d.x), "+f"(d.y), "+f"(d.z), "+f"(d.w)
        : "r"(a.x), "r"(a.y), "r"(a.z), "r"(a.w), "r"(b0), "r"(b1));
}

extern "C" __global__ void __launch_bounds__(THREADS, 2)
mobius_ws_kernel(const float* __restrict__ X,
                 const float* __restrict__ W,
                 const float* __restrict__ bias,
                 float* __restrict__ out,
                 int nrows)
{
    extern __shared__ __align__(16) char smem[];
    float* sbias = (float*)(smem + OFF_BIAS);
    float* sB2   = (float*)(smem + OFF_B2);
    float* rs2   = (float*)(smem + OFF_RS2);
    float* rsb   = (float*)(smem + OFF_RSB);
    float* cA    = (float*)(smem + OFF_CA);
    float* cB    = (float*)(smem + OFF_CB);

    const int tid  = threadIdx.x;
    const int lane = tid & 31;
    const int wid  = tid >> 5;
    const int g    = lane >> 2;
    const int cg   = lane & 3;

    if (tid < 128) sbias[tid] = bias[tid];

    // ---- W conversion (once, all 8 warps): warp wid = k-step s; fp16 ----
    {
        const float* wp0 = W + wid * 16 + 2 * cg;
        #pragma unroll
        for (int nt = 0; nt < 16; nt++) {
            int n = nt * 8 + g;
            const float* wp = wp0 + n * DIN;
            float2 u0 = *(const float2*)(wp);
            float2 u1 = *(const float2*)(wp + 8);
            uint2 vh;
            vh.x = packh(u0.y, u0.x);
            vh.y = packh(u1.y, u1.x);
            int p = nt >> 1, half = nt & 1;
            *(uint2*)(smem + OFF_WH + ((wid * 8 + p) * 32 + lane) * 16 + half * 8) = vh;
        }
    }
    __syncthreads();
    if (tid < 32) {
        float s = 0.f;
        #pragma unroll
        for (int i = 0; i < 4; i++) { float v = sbias[tid + 32 * i]; s = fmaf(v, v, s); }
        #pragma unroll
        for (int o = 16; o; o >>= 1) s += __shfl_xor_sync(0xffffffffu, s, o);
        if (tid == 0) *sB2 = s;
    }
    __syncthreads();   // last CTA-wide barrier

    const int ntiles = nrows / TILE;
    const int gstep  = gridDim.x;

    if (wid < 4) {
        // ================= PRODUCER: convert X tiles into staged frags ====
        const int p = wid;   // frag-row 0..3 (rows p*16 .. p*16+15)
        int i = 0;
        for (int t = blockIdx.x; t < ntiles; t += gstep, i++) {
            const int st = i & 1;
            if (i >= 2) bar_sync256(BAR_EMPTY(st));   // stage free

            const long long rowbase = (long long)t * TILE;
            const float* p0 = X + (rowbase + p * 16 + g) * DIN + 2 * cg;
            const float* p1 = p0 + 8 * DIN;
            float xa0 = 0.f, xa1 = 0.f;
            #pragma unroll
            for (int s = 0; s < 8; s++) {
                float2 v00 = *(const float2*)(p0 + 16 * s);
                float2 v01 = *(const float2*)(p0 + 16 * s + 8);
                float2 v10 = *(const float2*)(p1 + 16 * s);
                float2 v11 = *(const float2*)(p1 + 16 * s + 8);
                xa0 = fmaf(v00.x, v00.x, xa0); xa0 = fmaf(v00.y, v00.y, xa0);
                xa0 = fmaf(v01.x, v01.x, xa0); xa0 = fmaf(v01.y, v01.y, xa0);
                xa1 = fmaf(v10.x, v10.x, xa1); xa1 = fmaf(v10.y, v10.y, xa1);
                xa1 = fmaf(v11.x, v11.x, xa1); xa1 = fmaf(v11.y, v11.y, xa1);
                uint4 h, l;
                h.x = packh(v00.y, v00.x);
                h.y = packh(v10.y, v10.x);
                h.z = packh(v01.y, v01.x);
                h.w = packh(v11.y, v11.x);
                float2 e;
                e = unph(h.x); l.x = packh(v00.y - e.y, v00.x - e.x);
                e = unph(h.y); l.y = packh(v10.y - e.y, v10.x - e.x);
                e = unph(h.z); l.z = packh(v01.y - e.y, v01.x - e.x);
                e = unph(h.w); l.w = packh(v11.y - e.y, v11.x - e.x);
                int off = ((p * 8 + s) * 32 + lane) * 16;
                *(uint4*)(smem + AH_ST(st) + off) = h;
                *(uint4*)(smem + AL_ST(st) + off) = l;
            }
            xa0 += __shfl_xor_sync(0xffffffffu, xa0, 1);
            xa0 += __shfl_xor_sync(0xffffffffu, xa0, 2);
            xa1 += __shfl_xor_sync(0xffffffffu, xa1, 1);
            xa1 += __shfl_xor_sync(0xffffffffu, xa1, 2);
            if (cg == 0) {
                float* xn = (float*)(smem + OFF_XN2(st));
                xn[p * 16 + g]     = xa0;
                xn[p * 16 + g + 8] = xa1;
            }
            __threadfence_block();
            bar_arrive256(BAR_FULL(st));
        }
    } else {
        // ================= CONSUMER: MMA + epilogue + stores ==============
        const int c    = wid - 4;
        const int wm2  = c >> 1;    // m-half (32 rows)
        const int wn2  = c & 1;     // n-half (64 cols)
        const int ctid = tid - 128;

        float2 bj[8];
        #pragma unroll
        for (int j = 0; j < 8; j++)
            bj[j] = *(const float2*)(sbias + wn2 * 64 + j * 8 + 2 * cg);
        const float b2c = *sB2;

        int i = 0;
        for (int t = blockIdx.x; t < ntiles; t += gstep, i++) {
            const int st = i & 1;
            const long long rowbase = (long long)t * TILE;

            bar_sync256(BAR_FULL(st));   // frags + xn2 ready

            // ---- mainloop: warp tile m32 x n64, 2-pass fp16 ----
            float4 acc[2][8];
            #pragma unroll
            for (int ii = 0; ii < 2; ii++)
                #pragma unroll
                for (int j = 0; j < 8; j++) acc[ii][j] = make_float4(0.f, 0.f, 0.f, 0.f);

            #pragma unroll
            for (int s = 0; s < 8; s++) {
                uint4 ah[2], wh[4], al[2];
                #pragma unroll
                for (int ii = 0; ii < 2; ii++)
                    ah[ii] = *(const uint4*)(smem + AH_ST(st)
                              + (((wm2 * 2 + ii) * 8 + s) * 32 + lane) * 16);
                #pragma unroll
                for (int u = 0; u < 4; u++)
                    wh[u] = *(const uint4*)(smem + OFF_WH
                              + (((s * 8 + wn2 * 4 + u) * 32 + lane) * 16));
                #pragma unroll
                for (int ii = 0; ii < 2; ii++)
                    #pragma unroll
                    for (int u = 0; u < 4; u++) {
                        mma_f16(acc[ii][2*u],   ah[ii], wh[u].x, wh[u].y);
                        mma_f16(acc[ii][2*u+1], ah[ii], wh[u].z, wh[u].w);
                    }
                #pragma unroll
                for (int ii = 0; ii < 2; ii++)
                    al[ii] = *(const uint4*)(smem + AL_ST(st)
                              + (((wm2 * 2 + ii) * 8 + s) * 32 + lane) * 16);
                #pragma unroll
                for (int ii = 0; ii < 2; ii++)
                    #pragma unroll
                    for (int u = 0; u < 4; u++) {
                        mma_f16(acc[ii][2*u],   al[ii], wh[u].x, wh[u].y);
                        mma_f16(acc[ii][2*u+1], al[ii], wh[u].z, wh[u].w);
                    }
            }

            // ---- reductions per row: ||Mx||^2, <Mx,bias> ----
            #pragma unroll
            for (int ii = 0; ii < 2; ii++) {
                float s2r0 = 0.f, s2r1 = 0.f, sbr0 = 0.f, sbr1 = 0.f;
                #pragma unroll
                for (int j = 0; j < 8; j++) {
                    float4 d = acc[ii][j];
                    s2r0 = fmaf(d.x, d.x, s2r0); s2r0 = fmaf(d.y, d.y, s2r0);
                    s2r1 = fmaf(d.z, d.z, s2r1); s2r1 = fmaf(d.w, d.w, s2r1);
                    sbr0 = fmaf(d.x, bj[j].x, sbr0); sbr0 = fmaf(d.y, bj[j].y, sbr0);
                    sbr1 = fmaf(d.z, bj[j].x, sbr1); sbr1 = fmaf(d.w, bj[j].y, sbr1);
                }
                s2r0 += __shfl_xor_sync(0xffffffffu, s2r0, 1);
                s2r0 += __shfl_xor_sync(0xffffffffu, s2r0, 2);
                s2r1 += __shfl_xor_sync(0xffffffffu, s2r1, 1);
                s2r1 += __shfl_xor_sync(0xffffffffu, s2r1, 2);
                sbr0 += __shfl_xor_sync(0xffffffffu, sbr0, 1);
                sbr0 += __shfl_xor_sync(0xffffffffu, sbr0, 2);
                sbr1 += __shfl_xor_sync(0xffffffffu, sbr1, 1);
                sbr1 += __shfl_xor_sync(0xffffffffu, sbr1, 2);
                if (cg == 0) {
                    int r0 = wm2 * 32 + ii * 16 + g;
                    rs2[r0 * 2 + wn2]       = s2r0;
                    rs2[(r0 + 8) * 2 + wn2] = s2r1;
                    rsb[r0 * 2 + wn2]       = sbr0;
                    rsb[(r0 + 8) * 2 + wn2] = sbr1;
                }
            }
            bar_sync128(BAR_CONS);

            // ---- coef (consumer threads 0..63), reads stage xn2 ----
            if (ctid < TILE) {
                int r = ctid;
                const float* xn2st = (const float*)(smem + OFF_XN2(st));
                float mxn2 = rs2[r * 2] + rs2[r * 2 + 1];
                float dotb = rsb[r * 2] + rsb[r * 2 + 1];
                float xn  = fmaxf(sqrtf(xn2st[r]), 1e-15f);
                float mxn = fmaxf(sqrtf(mxn2),     1e-15f);
                float u   = fminf(xn, 1.0f - 1e-7f);
                float at  = 0.5f * (log1pf(u) - log1pf(-u));
                float sc  = tanhf(mxn / xn * at) / mxn;
                if (mxn <= 1e-10f) sc = 0.0f;
                float xy    = sc * dotb;
                float y2    = sc * sc * mxn2;
                float alpha = 1.0f + 2.0f * xy + b2c;
                float beta  = 1.0f - y2;
                float den   = fmaxf(1.0f + 2.0f * xy + y2 * b2c, 1e-15f);
                float A  = sc * alpha / den;
                float Bc = beta / den;
                float o2 = A * A * mxn2 + 2.0f * A * Bc * dotb + Bc * Bc * b2c;
                float on = fmaxf(sqrtf(o2), 1e-15f);
                float mxv = 1.0f - 1e-5f;
                float fpr = (on > mxv) ? (mxv / on) : 1.0f;
                cA[r] = A * fpr;
                cB[r] = Bc * fpr;
            }
            bar_sync128(BAR_CONS);

            // stage fully consumed (frags in mainloop, xn2 in coef)
            if (t + 2 * gstep < ntiles)
                bar_arrive256(BAR_EMPTY(st));

            // ---- stores: out = A[r]*Mx + B[r]*bias from regs ----
            #pragma unroll
            for (int ii = 0; ii < 2; ii++) {
                int r0 = wm2 * 32 + ii * 16 + g;
                float A0 = cA[r0],     B0 = cB[r0];
                float A1 = cA[r0 + 8], B1 = cB[r0 + 8];
                float* op0 = out + (rowbase + r0) * DOUT + wn2 * 64 + 2 * cg;
                float* op1 = op0 + 8 * DOUT;
                #pragma unroll
                for (int j = 0; j < 8; j++) {
                    float4 d = acc[ii][j];
                    float2 o0, o1;
                    o0.x = fmaf(A0, d.x, B0 * bj[j].x);
                    o0.y = fmaf(A0, d.y, B0 * bj[j].y);
                    o1.x = fmaf(A1, d.z, B1 * bj[j].x);
                    o1.y = fmaf(A1, d.w, B1 * bj[j].y);
                    *(float2*)(op0 + j * 8) = o0;
                    *(float2*)(op1 + j * 8) = o1;
                }
            }
            // cA/cB reuse is safe: next write happens after next BAR_CONS
            // sync, which this warp reaches only after these stores issue.
        }
    }
}

extern "C" void kernel_launch(void* const* d_in, const int* in_sizes, int n_in,
                              void* d_out, int out_size) {
    const float* X    = (const float*)d_in[0];
    const float* W    = (const float*)d_in[1];
    const float* bias = (const float*)d_in[2];
    float* out = (float*)d_out;

    int nrows = in_sizes[0] / DIN;

    cudaFuncSetAttribute(mobius_ws_kernel,
                         cudaFuncAttributeMaxDynamicSharedMemorySize, SMEM_TOTAL);

    int nsm = 148;
    cudaDeviceGetAttribute(&nsm, cudaDevAttrMultiProcessorCount, 0);
    int ntiles = nrows / TILE;
    int grid = 2 * nsm;
    if (grid > ntiles) grid = ntiles;

    mobius_ws_kernel<<<grid, THREADS, SMEM_TOTAL>>>(X, W, bias, out, nrows);
}

// round 9
// speedup vs baseline: 1.5132x; 1.3014x over previous
#include <cuda_runtime.h>
#include <cuda_fp16.h>
#include <cstdint>

#define DIN    128
#define DOUT   128
#define TILE   64
#define THREADS 256

// ---- smem layout (per CTA ~68KB -> 2 CTAs/SM) ----
#define OFF_WH     0                          // 8s x 8pairs x 32 x 16B = 32KB
#define AH_ST(s)   (32768 + (s)*16384)        // 16KB per stage (fp16 hi only)
#define OFF_BIAS   65536                      // 128 f32
#define OFF_B2     66048
#define OFF_XN2(s) (66064 + (s)*256)          // [64] f32 per stage
#define OFF_RS2    66576                      // [64][4] f32
#define OFF_RSB    67600                      // [64][4] f32
#define OFF_CA     68624
#define OFF_CB     68880
#define SMEM_TOTAL 69136

// named barriers: 1,2 = full(stage), 3,4 = empty(stage), 5 = consumer-internal
#define BAR_FULL(s)  (1 + (s))
#define BAR_EMPTY(s) (3 + (s))
#define BAR_CONS     5

__device__ __forceinline__ void bar_sync256(int id) {
    asm volatile("bar.sync %0, %1;" :: "r"(id), "r"(256) : "memory");
}
__device__ __forceinline__ void bar_arrive256(int id) {
    asm volatile("bar.arrive %0, %1;" :: "r"(id), "r"(256) : "memory");
}
__device__ __forceinline__ void bar_sync128(int id) {
    asm volatile("bar.sync %0, %1;" :: "r"(id), "r"(128) : "memory");
}

__device__ __forceinline__ uint32_t packh(float hi, float lo) {
    uint32_t r; asm("cvt.rn.f16x2.f32 %0, %1, %2;" : "=r"(r) : "f"(hi), "f"(lo)); return r;
}
__device__ __forceinline__ void mma_f16(float4& d, const uint4& a, uint32_t b0, uint32_t b1) {
    asm volatile("mma.sync.aligned.m16n8k16.row.col.f32.f16.f16.f32 "
        "{%0,%1,%2,%3}, {%4,%5,%6,%7}, {%8,%9}, {%0,%1,%2,%3};"
        : "+f"(d.x), "+f"(d.y), "+f"(d.z), "+f"(d.w)
        : "r"(a.x), "r"(a.y), "r"(a.z), "r"(a.w), "r"(b0), "r"(b1));
}

extern "C" __global__ void __launch_bounds__(THREADS, 2)
mobius_ws1p_kernel(const float* __restrict__ X,
                   const float* __restrict__ W,
                   const float* __restrict__ bias,
                   float* __restrict__ out,
                   int nrows)
{
    extern __shared__ __align__(16) char smem[];
    float* sbias = (float*)(smem + OFF_BIAS);
    float* sB2   = (float*)(smem + OFF_B2);
    float* rs2   = (float*)(smem + OFF_RS2);
    float* rsb   = (float*)(smem + OFF_RSB);
    float* cA    = (float*)(smem + OFF_CA);
    float* cB    = (float*)(smem + OFF_CB);

    const int tid  = threadIdx.x;
    const int lane = tid & 31;
    const int wid  = tid >> 5;
    const int g    = lane >> 2;
    const int cg   = lane & 3;

    if (tid < 128) sbias[tid] = bias[tid];

    // ---- W conversion (once, all 8 warps): warp wid = k-step s; fp16 hi ----
    {
        const float* wp0 = W + wid * 16 + 2 * cg;
        #pragma unroll
        for (int nt = 0; nt < 16; nt++) {
            int n = nt * 8 + g;
            const float* wp = wp0 + n * DIN;
            float2 u0 = *(const float2*)(wp);
            float2 u1 = *(const float2*)(wp + 8);
            uint2 vh;
            vh.x = packh(u0.y, u0.x);
            vh.y = packh(u1.y, u1.x);
            int p = nt >> 1, half = nt & 1;
            *(uint2*)(smem + OFF_WH + ((wid * 8 + p) * 32 + lane) * 16 + half * 8) = vh;
        }
    }
    __syncthreads();
    if (tid < 32) {
        float s = 0.f;
        #pragma unroll
        for (int i = 0; i < 4; i++) { float v = sbias[tid + 32 * i]; s = fmaf(v, v, s); }
        #pragma unroll
        for (int o = 16; o; o >>= 1) s += __shfl_xor_sync(0xffffffffu, s, o);
        if (tid == 0) *sB2 = s;
    }
    __syncthreads();   // last CTA-wide barrier

    const int ntiles = nrows / TILE;
    const int gstep  = gridDim.x;

    if (wid < 4) {
        // ========== PRODUCER: X -> fp16 frags (hi only) + xn2 ==========
        const int p = wid;   // frag-row p: rows p*16+g, p*16+8+g
        int i = 0;
        for (int t = blockIdx.x; t < ntiles; t += gstep, i++) {
            const int st = i & 1;
            if (i >= 2) bar_sync256(BAR_EMPTY(st));

            const long long rowbase = (long long)t * TILE;
            const float* p0 = X + (rowbase + p * 16 + g) * DIN + 2 * cg;
            const float* p1 = p0 + 8 * DIN;
            float xa0 = 0.f, xa1 = 0.f;
            #pragma unroll
            for (int s = 0; s < 8; s++) {
                float2 v00 = *(const float2*)(p0 + 16 * s);
                float2 v01 = *(const float2*)(p0 + 16 * s + 8);
                float2 v10 = *(const float2*)(p1 + 16 * s);
                float2 v11 = *(const float2*)(p1 + 16 * s + 8);
                xa0 = fmaf(v00.x, v00.x, xa0); xa0 = fmaf(v00.y, v00.y, xa0);
                xa0 = fmaf(v01.x, v01.x, xa0); xa0 = fmaf(v01.y, v01.y, xa0);
                xa1 = fmaf(v10.x, v10.x, xa1); xa1 = fmaf(v10.y, v10.y, xa1);
                xa1 = fmaf(v11.x, v11.x, xa1); xa1 = fmaf(v11.y, v11.y, xa1);
                uint4 h;
                h.x = packh(v00.y, v00.x);
                h.y = packh(v10.y, v10.x);
                h.z = packh(v01.y, v01.x);
                h.w = packh(v11.y, v11.x);
                *(uint4*)(smem + AH_ST(st) + ((p * 8 + s) * 32 + lane) * 16) = h;
            }
            xa0 += __shfl_xor_sync(0xffffffffu, xa0, 1);
            xa0 += __shfl_xor_sync(0xffffffffu, xa0, 2);
            xa1 += __shfl_xor_sync(0xffffffffu, xa1, 1);
            xa1 += __shfl_xor_sync(0xffffffffu, xa1, 2);
            if (cg == 0) {
                float* xn = (float*)(smem + OFF_XN2(st));
                xn[p * 16 + g]     = xa0;
                xn[p * 16 + g + 8] = xa1;
            }
            __threadfence_block();
            bar_arrive256(BAR_FULL(st));
        }
    } else {
        // ========== CONSUMER: MMA (m64 x n32) + epilogue + stores ==========
        const int c    = wid - 4;      // n-quarter: cols c*32 .. c*32+31
        const int ctid = tid - 128;
        const float b2c = *sB2;

        int i = 0;
        for (int t = blockIdx.x; t < ntiles; t += gstep, i++) {
            const int st = i & 1;
            const long long rowbase = (long long)t * TILE;

            bar_sync256(BAR_FULL(st));

            // ---- mainloop: 1-pass fp16, warp tile m64 x n32 ----
            float4 acc[4][4];
            #pragma unroll
            for (int ii = 0; ii < 4; ii++)
                #pragma unroll
                for (int j = 0; j < 4; j++) acc[ii][j] = make_float4(0.f, 0.f, 0.f, 0.f);

            #pragma unroll
            for (int s = 0; s < 8; s++) {
                uint4 ah[4], wh[2];
                #pragma unroll
                for (int ii = 0; ii < 4; ii++)
                    ah[ii] = *(const uint4*)(smem + AH_ST(st)
                              + ((ii * 8 + s) * 32 + lane) * 16);
                #pragma unroll
                for (int u = 0; u < 2; u++)
                    wh[u] = *(const uint4*)(smem + OFF_WH
                              + ((s * 8 + c * 2 + u) * 32 + lane) * 16);
                #pragma unroll
                for (int ii = 0; ii < 4; ii++)
                    #pragma unroll
                    for (int u = 0; u < 2; u++) {
                        mma_f16(acc[ii][2*u],   ah[ii], wh[u].x, wh[u].y);
                        mma_f16(acc[ii][2*u+1], ah[ii], wh[u].z, wh[u].w);
                    }
            }

            // ---- reductions per row: ||Mx||^2, <Mx,bias> (bias via LDS) ----
            float2 bj[4];
            #pragma unroll
            for (int j = 0; j < 4; j++)
                bj[j] = *(const float2*)(sbias + c * 32 + j * 8 + 2 * cg);

            #pragma unroll
            for (int ii = 0; ii < 4; ii++) {
                float s2r0 = 0.f, s2r1 = 0.f, sbr0 = 0.f, sbr1 = 0.f;
                #pragma unroll
                for (int j = 0; j < 4; j++) {
                    float4 d = acc[ii][j];
                    s2r0 = fmaf(d.x, d.x, s2r0); s2r0 = fmaf(d.y, d.y, s2r0);
                    s2r1 = fmaf(d.z, d.z, s2r1); s2r1 = fmaf(d.w, d.w, s2r1);
                    sbr0 = fmaf(d.x, bj[j].x, sbr0); sbr0 = fmaf(d.y, bj[j].y, sbr0);
                    sbr1 = fmaf(d.z, bj[j].x, sbr1); sbr1 = fmaf(d.w, bj[j].y, sbr1);
                }
                s2r0 += __shfl_xor_sync(0xffffffffu, s2r0, 1);
                s2r0 += __shfl_xor_sync(0xffffffffu, s2r0, 2);
                s2r1 += __shfl_xor_sync(0xffffffffu, s2r1, 1);
                s2r1 += __shfl_xor_sync(0xffffffffu, s2r1, 2);
                sbr0 += __shfl_xor_sync(0xffffffffu, sbr0, 1);
                sbr0 += __shfl_xor_sync(0xffffffffu, sbr0, 2);
                sbr1 += __shfl_xor_sync(0xffffffffu, sbr1, 1);
                sbr1 += __shfl_xor_sync(0xffffffffu, sbr1, 2);
                if (cg == 0) {
                    int r0 = ii * 16 + g;
                    rs2[r0 * 4 + c]       = s2r0;
                    rs2[(r0 + 8) * 4 + c] = s2r1;
                    rsb[r0 * 4 + c]       = sbr0;
                    rsb[(r0 + 8) * 4 + c] = sbr1;
                }
            }
            bar_sync128(BAR_CONS);

            // ---- per-row coefficients ----
            if (ctid < TILE) {
                int r = ctid;
                const float* xn2st = (const float*)(smem + OFF_XN2(st));
                float4 a4 = *(const float4*)(rs2 + r * 4);
                float4 b4 = *(const float4*)(rsb + r * 4);
                float mxn2 = (a4.x + a4.y) + (a4.z + a4.w);
                float dotb = (b4.x + b4.y) + (b4.z + b4.w);
                float xn  = fmaxf(sqrtf(xn2st[r]), 1e-15f);
                float mxn = fmaxf(sqrtf(mxn2),     1e-15f);
                float u   = fminf(xn, 1.0f - 1e-7f);
                float at  = 0.5f * (log1pf(u) - log1pf(-u));
                float sc  = tanhf(mxn / xn * at) / mxn;
                if (mxn <= 1e-10f) sc = 0.0f;
                float xy    = sc * dotb;
                float y2    = sc * sc * mxn2;
                float alpha = 1.0f + 2.0f * xy + b2c;
                float beta  = 1.0f - y2;
                float den   = fmaxf(1.0f + 2.0f * xy + y2 * b2c, 1e-15f);
                float A  = sc * alpha / den;
                float Bc = beta / den;
                float o2 = A * A * mxn2 + 2.0f * A * Bc * dotb + Bc * Bc * b2c;
                float on = fmaxf(sqrtf(o2), 1e-15f);
                float mxv = 1.0f - 1e-5f;
                float fpr = (on > mxv) ? (mxv / on) : 1.0f;
                cA[r] = A * fpr;
                cB[r] = Bc * fpr;
            }
            bar_sync128(BAR_CONS);

            // stage fully consumed (frags in mainloop, xn2 in coef)
            if (t + 2 * gstep < ntiles)
                bar_arrive256(BAR_EMPTY(st));

            // ---- stores: out = A[r]*Mx + B[r]*bias from regs ----
            #pragma unroll
            for (int ii = 0; ii < 4; ii++) {
                int r0 = ii * 16 + g;
                float A0 = cA[r0],     B0 = cB[r0];
                float A1 = cA[r0 + 8], B1 = cB[r0 + 8];
                float* op0 = out + (rowbase + r0) * DOUT + c * 32 + 2 * cg;
                float* op1 = op0 + 8 * DOUT;
                #pragma unroll
                for (int j = 0; j < 4; j++) {
                    float4 d = acc[ii][j];
                    float2 o0, o1;
                    o0.x = fmaf(A0, d.x, B0 * bj[j].x);
                    o0.y = fmaf(A0, d.y, B0 * bj[j].y);
                    o1.x = fmaf(A1, d.z, B1 * bj[j].x);
                    o1.y = fmaf(A1, d.w, B1 * bj[j].y);
                    *(float2*)(op0 + j * 8) = o0;
                    *(float2*)(op1 + j * 8) = o1;
                }
            }
            // cA/cB reuse safe: next write is after next BAR_CONS sync,
            // reached by this warp only after these stores issue.
        }
    }
}

extern "C" void kernel_launch(void* const* d_in, const int* in_sizes, int n_in,
                              void* d_out, int out_size) {
    const float* X    = (const float*)d_in[0];
    const float* W    = (const float*)d_in[1];
    const float* bias = (const float*)d_in[2];
    float* out = (float*)d_out;

    int nrows = in_sizes[0] / DIN;

    cudaFuncSetAttribute(mobius_ws1p_kernel,
                         cudaFuncAttributeMaxDynamicSharedMemorySize, SMEM_TOTAL);

    int nsm = 148;
    cudaDeviceGetAttribute(&nsm, cudaDevAttrMultiProcessorCount, 0);
    int ntiles = nrows / TILE;
    int grid = 2 * nsm;
    if (grid > ntiles) grid = ntiles;

    mobius_ws1p_kernel<<<grid, THREADS, SMEM_TOTAL>>>(X, W, bias, out, nrows);
}